// round 2
// baseline (speedup 1.0000x reference)
#include <cuda_runtime.h>
#include <cuda_bf16.h>
#include <cstdint>

// ---------------- problem constants ----------------
#define NTOK   16384      // S-2 tokens
#define HIN    768        // input hidden
#define NPACK  1536       // packed gate columns: [i_f,g_f,o_f, i_b,g_b,o_b] x 256
#define HIDC   512        // enc width
#define NTAG   20
#define NCHUNK 128
#define CLEN   128        // NCHUNK*CLEN = NTOK
#define NEGV   (-10000.0f)

// ---------------- device scratch (no allocs allowed) ----------------
__device__ float d_Wt[HIN * NPACK];          // packed transposed weights [k][n]
__device__ float d_biasC[NPACK];             // b_ih + b_hh for packed cols
__device__ float d_gates[NTOK * NPACK];      // pre-activation gates
__device__ float d_enc[NTOK * HIDC];         // lstm outputs (concat f,b)
__device__ float d_feats[NTOK * NTAG];       // tag scores
__device__ float d_P[NCHUNK * NTAG * NTAG];  // per-chunk maxplus products
__device__ float d_fvs[NCHUNK * NTAG];       // chunk-start viterbi vectors
__device__ float d_finalfv[NTAG];
__device__ unsigned char d_bps[NTOK * NTAG]; // backpointers
__device__ unsigned char d_Wc[NCHUNK * NTAG];// chunk backtrack tables
__device__ unsigned char d_r[NCHUNK];        // chunk-boundary path states

// ---------------- K0: pack weights + bias ----------------
// packed col n: dir = n/768, local = n%768, src row r = local<256? local : local+256
__global__ void pack_weights(const float* __restrict__ wf, const float* __restrict__ wb,
                             const float* __restrict__ bihf, const float* __restrict__ bhhf,
                             const float* __restrict__ bihb, const float* __restrict__ bhhb) {
    int idx = blockIdx.x * blockDim.x + threadIdx.x;
    if (idx >= HIN * NPACK) return;
    int k = idx / NPACK, n = idx % NPACK;
    int dir = (n >= 768) ? 1 : 0;
    int local = n - dir * 768;
    int r = local + (local < 256 ? 0 : 256);
    const float* w = dir ? wb : wf;
    d_Wt[idx] = w[r * HIN + k];
    if (k == 0) {
        d_biasC[n] = dir ? (bihb[r] + bhhb[r]) : (bihf[r] + bhhf[r]);
    }
}

// ---------------- K1: gates GEMM  C[M=NTOK][N=NPACK] = A[M][768] * Wt ----------------
#define BM 128
#define BN 128
#define BKK 16
__global__ __launch_bounds__(256) void gemm_gates(const float* __restrict__ A) {
    __shared__ float As[BKK][BM];
    __shared__ float Bs[BKK][BN];
    int tid = threadIdx.x;
    int bm = blockIdx.y, bn = blockIdx.x;
    const float* Ablk = A + bm * BM * HIN;
    const float* Bblk = d_Wt + bn * BN;

    float acc[8][8];
#pragma unroll
    for (int i = 0; i < 8; i++)
#pragma unroll
        for (int j = 0; j < 8; j++) acc[i][j] = 0.f;

    int r0 = (tid >> 4) * 8;
    int c0 = (tid & 15) * 8;

    for (int kt = 0; kt < HIN; kt += BKK) {
#pragma unroll
        for (int i = 0; i < 2; i++) {
            int flat = tid + i * 256;
            int row = flat >> 2, kq = (flat & 3) * 4;
            float4 v = *(const float4*)(Ablk + row * HIN + kt + kq);
            As[kq + 0][row] = v.x;
            As[kq + 1][row] = v.y;
            As[kq + 2][row] = v.z;
            As[kq + 3][row] = v.w;
            int kr = flat >> 5, nq = (flat & 31) * 4;
            float4 w = *(const float4*)(Bblk + (kt + kr) * NPACK + nq);
            *(float4*)&Bs[kr][nq] = w;
        }
        __syncthreads();
#pragma unroll
        for (int kk = 0; kk < BKK; kk++) {
            float a[8], b[8];
            *(float4*)&a[0] = *(const float4*)&As[kk][r0];
            *(float4*)&a[4] = *(const float4*)&As[kk][r0 + 4];
            *(float4*)&b[0] = *(const float4*)&Bs[kk][c0];
            *(float4*)&b[4] = *(const float4*)&Bs[kk][c0 + 4];
#pragma unroll
            for (int i = 0; i < 8; i++)
#pragma unroll
                for (int j = 0; j < 8; j++) acc[i][j] += a[i] * b[j];
        }
        __syncthreads();
    }
    // epilogue: add bias, store
    float bias[8];
#pragma unroll
    for (int j = 0; j < 8; j++) bias[j] = d_biasC[bn * BN + c0 + j];
#pragma unroll
    for (int i = 0; i < 8; i++) {
        int row = bm * BM + r0 + i;
        float* dst = d_gates + row * NPACK + bn * BN + c0;
        float4 v0, v1;
        v0.x = acc[i][0] + bias[0]; v0.y = acc[i][1] + bias[1];
        v0.z = acc[i][2] + bias[2]; v0.w = acc[i][3] + bias[3];
        v1.x = acc[i][4] + bias[4]; v1.y = acc[i][5] + bias[5];
        v1.z = acc[i][6] + bias[6]; v1.w = acc[i][7] + bias[7];
        *(float4*)dst = v0;
        *(float4*)(dst + 4) = v1;
    }
}

// ---------------- K2: activation -> enc ----------------
__global__ void activation_kernel() {
    int idx = blockIdx.x * blockDim.x + threadIdx.x;  // over NTOK*HIDC
    int m = idx >> 9, j = idx & 511;
    int dir = j >> 8, jj = j & 255;
    const float* gr = d_gates + m * NPACK + dir * 768 + jj;
    float iv = gr[0], gv = gr[256], ov = gr[512];
    float si = 1.f / (1.f + expf(-iv));
    float cc = si * tanhf(gv);
    float so = 1.f / (1.f + expf(-ov));
    d_enc[idx] = so * tanhf(cc);
}

// ---------------- K3: feats = enc @ w_tag^T + b_tag ----------------
__global__ __launch_bounds__(128) void feats_kernel(const float* __restrict__ wtag,
                                                    const float* __restrict__ btag) {
    __shared__ float wsm[NTAG * HIDC];
    __shared__ float bsm[NTAG];
    for (int i = threadIdx.x; i < NTAG * HIDC; i += 128) wsm[i] = wtag[i];
    if (threadIdx.x < NTAG) bsm[threadIdx.x] = btag[threadIdx.x];
    __syncthreads();
    int warp = threadIdx.x >> 5, lane = threadIdx.x & 31;
    int m = blockIdx.x * 4 + warp;
    float e[16];
#pragma unroll
    for (int q = 0; q < 16; q++) e[q] = d_enc[m * HIDC + q * 32 + lane];
#pragma unroll
    for (int t = 0; t < NTAG; t++) {
        float s = 0.f;
#pragma unroll
        for (int q = 0; q < 16; q++) s += e[q] * wsm[t * HIDC + q * 32 + lane];
#pragma unroll
        for (int off = 16; off > 0; off >>= 1) s += __shfl_xor_sync(0xffffffffu, s, off);
        if (lane == 0) d_feats[m * NTAG + t] = s + bsm[t];
    }
}

// ---------------- V1: per-chunk maxplus matrix products ----------------
// M_t[j][k] = trans[j][k] + feat_t[j];  P_c = M_{hi} (x) ... (x) M_{lo}
__global__ __launch_bounds__(512) void viterbi_chunk_prod(const float* __restrict__ trans) {
    __shared__ float fsm[CLEN * NTAG];
    __shared__ float P[2][NTAG][NTAG];
    int c = blockIdx.x, tid = threadIdx.x;
    for (int i = tid; i < CLEN * NTAG; i += 512) fsm[i] = d_feats[c * CLEN * NTAG + i];
    __syncthreads();
    int j = tid / NTAG, k = tid % NTAG;
    bool act = (tid < NTAG * NTAG);
    float tr[NTAG];
    if (act) {
#pragma unroll
        for (int m = 0; m < NTAG; m++) tr[m] = trans[j * NTAG + m];
        P[0][j][k] = trans[j * NTAG + k] + fsm[j];  // t=0
    }
    __syncthreads();
    int buf = 0;
    for (int t = 1; t < CLEN; t++) {
        if (act) {
            float v = -1e30f;
#pragma unroll
            for (int m = 0; m < NTAG; m++) v = fmaxf(v, tr[m] + P[buf][m][k]);
            P[buf ^ 1][j][k] = v + fsm[t * NTAG + j];
        }
        buf ^= 1;
        __syncthreads();
    }
    if (act) d_P[c * NTAG * NTAG + j * NTAG + k] = P[buf][j][k];
}

// ---------------- V2: sequential scan over chunk products -> chunk-start fvs ----------------
__global__ void viterbi_scan() {
    __shared__ float Ps[NTAG * NTAG];
    __shared__ float fvsm[NTAG];
    int lane = threadIdx.x;  // 32 threads
    float fv = (lane == 18) ? 0.f : NEGV;  // START=18
    for (int c = 0; c < NCHUNK; c++) {
        for (int i = lane; i < NTAG * NTAG; i += 32) Ps[i] = d_P[c * NTAG * NTAG + i];
        if (lane < NTAG) { d_fvs[c * NTAG + lane] = fv; fvsm[lane] = fv; }
        __syncwarp();
        float nf = -1e30f;
        if (lane < NTAG) {
#pragma unroll
            for (int k = 0; k < NTAG; k++) nf = fmaxf(nf, Ps[lane * NTAG + k] + fvsm[k]);
        }
        __syncwarp();
        if (lane < NTAG) fv = nf;
    }
}

// ---------------- V3: per-chunk forward, emit backpointers ----------------
__global__ void viterbi_forward(const float* __restrict__ trans) {
    __shared__ float fsm[CLEN * NTAG];
    int c = blockIdx.x, lane = threadIdx.x;
    for (int i = lane; i < CLEN * NTAG; i += 32) fsm[i] = d_feats[c * CLEN * NTAG + i];
    __syncwarp();
    bool act = lane < NTAG;
    float tr[NTAG];
    if (act) {
#pragma unroll
        for (int m = 0; m < NTAG; m++) tr[m] = trans[lane * NTAG + m];
    }
    float fv = act ? d_fvs[c * NTAG + lane] : -1e30f;
    unsigned char* bp = d_bps + c * CLEN * NTAG;
    for (int t = 0; t < CLEN; t++) {
        float best = -1e30f;
        int bi = 0;
#pragma unroll
        for (int k = 0; k < NTAG; k++) {
            float v = __shfl_sync(0xffffffffu, fv, k);
            if (act) {
                v += tr[k];
                if (v > best) { best = v; bi = k; }  // first-max tiebreak
            }
        }
        if (act) {
            bp[t * NTAG + lane] = (unsigned char)bi;
            fv = best + fsm[t * NTAG + lane];
        }
    }
    if (c == NCHUNK - 1 && act) d_finalfv[lane] = fv;
}

// ---------------- B1: per-chunk backtrack composition tables ----------------
__global__ void backtrack_tables() {
    __shared__ unsigned char b[CLEN * NTAG];
    int c = blockIdx.x, lane = threadIdx.x;
    const uint4* src = (const uint4*)(d_bps + c * CLEN * NTAG);
    uint4* dstv = (uint4*)b;
    for (int i = lane; i < (CLEN * NTAG) / 16; i += 32) dstv[i] = src[i];
    __syncwarp();
    if (lane < NTAG) {
        int x = lane;
        for (int t = CLEN - 1; t >= 0; t--) x = b[t * NTAG + x];
        d_Wc[c * NTAG + lane] = (unsigned char)x;
    }
}

// ---------------- B2: terminal argmax + chunk-boundary scan ----------------
__global__ void terminal_and_scan(const float* __restrict__ trans, float* __restrict__ out) {
    __shared__ unsigned char Wsm[NCHUNK * NTAG];
    int lane = threadIdx.x;
    const uint4* src = (const uint4*)d_Wc;
    for (int i = lane; i < (NCHUNK * NTAG) / 16; i += 32) ((uint4*)Wsm)[i] = src[i];
    float term = (lane < NTAG) ? d_finalfv[lane] + trans[19 * NTAG + lane] : -1e30f;  // STOP=19
    __syncwarp();
    float best = -1e30f;
    int bi = 0;
#pragma unroll
    for (int k = 0; k < NTAG; k++) {
        float v = __shfl_sync(0xffffffffu, term, k);
        if (v > best) { best = v; bi = k; }
    }
    if (lane == 0) {
        out[0] = best;  // path_score
        int r = bi;
        d_r[NCHUNK - 1] = (unsigned char)r;
        for (int c = NCHUNK - 1; c >= 1; c--) {
            r = Wsm[c * NTAG + r];
            d_r[c - 1] = (unsigned char)r;
        }
    }
}

// ---------------- B3: per-chunk path emission ----------------
__global__ void backtrack_emit(float* __restrict__ out) {
    __shared__ unsigned char b[CLEN * NTAG];
    int c = blockIdx.x, lane = threadIdx.x;
    const uint4* src = (const uint4*)(d_bps + c * CLEN * NTAG);
    uint4* dstv = (uint4*)b;
    for (int i = lane; i < (CLEN * NTAG) / 16; i += 32) dstv[i] = src[i];
    __syncwarp();
    if (lane == 0) {
        int x = d_r[c];
        float* o = out + 1 + c * CLEN;
        for (int t = CLEN - 1; t >= 0; t--) {
            o[t] = (float)x;
            x = b[t * NTAG + x];
        }
    }
}

// ---------------- launch ----------------
extern "C" void kernel_launch(void* const* d_in, const int* in_sizes, int n_in,
                              void* d_out, int out_size) {
    const float* x      = (const float*)d_in[0];
    const float* w_ih_f = (const float*)d_in[1];
    const float* b_ih_f = (const float*)d_in[3];
    const float* b_hh_f = (const float*)d_in[4];
    const float* w_ih_b = (const float*)d_in[5];
    const float* b_ih_b = (const float*)d_in[7];
    const float* b_hh_b = (const float*)d_in[8];
    const float* w_tag  = (const float*)d_in[9];
    const float* b_tag  = (const float*)d_in[10];
    const float* trans  = (const float*)d_in[11];
    float* out = (float*)d_out;

    pack_weights<<<(HIN * NPACK + 255) / 256, 256>>>(w_ih_f, w_ih_b, b_ih_f, b_hh_f, b_ih_b, b_hh_b);

    dim3 ggrid(NPACK / BN, NTOK / BM);
    gemm_gates<<<ggrid, 256>>>(x + HIN);  // skip first token (x[0,1:-1,:])

    activation_kernel<<<(NTOK * HIDC) / 256, 256>>>();
    feats_kernel<<<NTOK / 4, 128>>>(w_tag, b_tag);

    viterbi_chunk_prod<<<NCHUNK, 512>>>(trans);
    viterbi_scan<<<1, 32>>>();
    viterbi_forward<<<NCHUNK, 32>>>(trans);
    backtrack_tables<<<NCHUNK, 32>>>();
    terminal_and_scan<<<1, 32>>>(trans, out);
    backtrack_emit<<<NCHUNK, 32>>>(out);
}